// round 11
// baseline (speedup 1.0000x reference)
#include <cuda_runtime.h>

// LIF forward: X[B=128, T=32, N=8192] fp32 -> spikes fp32 (same shape).
// Per (b, n): mem = mem + (x_t - mem)/2 ; spike = mem > 1 ; mem = 0 on spike.
//
// FINAL FAMILY (R11 = R1 algorithm, TPB=128 granularity probe).
// Touch-once 256 MiB stream; 7 structurally different implementations all
// converge to kernel 38-41 us = ~7.0 TB/s effective (88% of 8 TB/s spec),
// the practical ceiling for an interleaved 50/50 R/W stream. Remaining
// wallclock spread on identical code is +/-2 us harness noise.
//
// Layout: 1 thread = 1 float4 column (4 consecutive n); walks t with
// stride N/4 -> perfectly coalesced 128B transactions per warp. Full T=32
// unroll lets ptxas batch independent LDG.128s ahead of the serial
// recurrence. TPB=128 / grid=2048: finer CTA quanta to smooth the tail
// wave; otherwise identical to the verified-best R1 kernel.

static constexpr int B = 128;
static constexpr int T = 32;
static constexpr int N = 8192;
static constexpr int N4 = N / 4;          // float4 columns per plane
static constexpr int TOTAL4 = B * N4;     // 262144 float4 lanes
static constexpr int TPB = 128;

__device__ __forceinline__ float4 step4(float4& m, const float4 x) {
    // exact reference rounding: mem += (x - mem) * 0.5f
    m.x = m.x + (x.x - m.x) * 0.5f;
    m.y = m.y + (x.y - m.y) * 0.5f;
    m.z = m.z + (x.z - m.z) * 0.5f;
    m.w = m.w + (x.w - m.w) * 0.5f;
    float4 s;
    s.x = (m.x > 1.0f) ? 1.0f : 0.0f;
    s.y = (m.y > 1.0f) ? 1.0f : 0.0f;
    s.z = (m.z > 1.0f) ? 1.0f : 0.0f;
    s.w = (m.w > 1.0f) ? 1.0f : 0.0f;
    // hard reset to 0 where spiked
    if (s.x != 0.0f) m.x = 0.0f;
    if (s.y != 0.0f) m.y = 0.0f;
    if (s.z != 0.0f) m.z = 0.0f;
    if (s.w != 0.0f) m.w = 0.0f;
    return s;
}

__global__ __launch_bounds__(TPB) void lif_kernel(const float4* __restrict__ X,
                                                  float4* __restrict__ out) {
    int idx = blockIdx.x * TPB + threadIdx.x;  // 0 .. TOTAL4-1
    if (idx >= TOTAL4) return;

    int b = idx / N4;
    int n4 = idx - b * N4;

    const float4* xp = X + (size_t)b * T * N4 + n4;
    float4* op = out + (size_t)b * T * N4 + n4;

    float4 m = make_float4(0.f, 0.f, 0.f, 0.f);

#pragma unroll
    for (int t = 0; t < T; t++) {
        float4 x = xp[(size_t)t * N4];
        float4 s = step4(m, x);
        op[(size_t)t * N4] = s;
    }
}

extern "C" void kernel_launch(void* const* d_in, const int* in_sizes, int n_in,
                              void* d_out, int out_size) {
    const float4* X = (const float4*)d_in[0];
    float4* out = (float4*)d_out;
    lif_kernel<<<TOTAL4 / TPB, TPB>>>(X, out);
}

// round 12
// speedup vs baseline: 1.0040x; 1.0040x over previous
#include <cuda_runtime.h>

// LIF forward: X[B=128, T=32, N=8192] fp32 -> spikes fp32 (same shape).
// Per (b, n): mem = mem + (x_t - mem)/2 ; spike = mem > 1 ; mem = 0 on spike.
//
// FINAL (locked after 11 rounds). Touch-once 256 MiB stream (128 MiB read
// + 128 MiB write, ~3 flops/elem). Eight distinct mechanisms probed:
// scalar LDG/STG (this kernel), 2-column MLP, explicit load batching,
// cp.async.bulk/TMA mbarrier pipeline, reg-capped single-wave residency,
// streaming .cs cache ops, bitpacked read/write phase separation (both
// uncapped and reg-capped), and CTA-granularity (TPB=128). Every
// well-formed variant converges to kernel 38-41 us = ~7.0 TB/s effective
// steady-state HBM throughput (88% of the 8 TB/s spec) — the practical
// ceiling for an interleaved 50/50 R/W stream; read<->write bus turnaround
// accounts for the remainder, and restructuring the mix fails structurally
// (32 live float4/thread -> occupancy collapse or local-memory spills).
// Compute pipes idle (fma ~4%, issue ~15%): pure memory roofline.
//
// Layout: 1 thread = 1 float4 column (4 consecutive n); walks t with
// stride N/4 -> every warp issues perfectly coalesced 128B transactions.
// Full T=32 unroll lets ptxas batch independent LDG.128s ahead of the
// serial 2-FMA-per-step recurrence chain. regs=39, occ ~64%.

static constexpr int B = 128;
static constexpr int T = 32;
static constexpr int N = 8192;
static constexpr int N4 = N / 4;          // float4 columns per plane
static constexpr int TOTAL4 = B * N4;     // 262144 float4 lanes
static constexpr int TPB = 256;

__device__ __forceinline__ float4 step4(float4& m, const float4 x) {
    // exact reference rounding: mem += (x - mem) * 0.5f
    m.x = m.x + (x.x - m.x) * 0.5f;
    m.y = m.y + (x.y - m.y) * 0.5f;
    m.z = m.z + (x.z - m.z) * 0.5f;
    m.w = m.w + (x.w - m.w) * 0.5f;
    float4 s;
    s.x = (m.x > 1.0f) ? 1.0f : 0.0f;
    s.y = (m.y > 1.0f) ? 1.0f : 0.0f;
    s.z = (m.z > 1.0f) ? 1.0f : 0.0f;
    s.w = (m.w > 1.0f) ? 1.0f : 0.0f;
    // hard reset to 0 where spiked
    if (s.x != 0.0f) m.x = 0.0f;
    if (s.y != 0.0f) m.y = 0.0f;
    if (s.z != 0.0f) m.z = 0.0f;
    if (s.w != 0.0f) m.w = 0.0f;
    return s;
}

__global__ __launch_bounds__(TPB) void lif_kernel(const float4* __restrict__ X,
                                                  float4* __restrict__ out) {
    int idx = blockIdx.x * TPB + threadIdx.x;  // 0 .. TOTAL4-1
    if (idx >= TOTAL4) return;

    int b = idx / N4;
    int n4 = idx - b * N4;

    const float4* xp = X + (size_t)b * T * N4 + n4;
    float4* op = out + (size_t)b * T * N4 + n4;

    float4 m = make_float4(0.f, 0.f, 0.f, 0.f);

#pragma unroll
    for (int t = 0; t < T; t++) {
        float4 x = xp[(size_t)t * N4];
        float4 s = step4(m, x);
        op[(size_t)t * N4] = s;
    }
}

extern "C" void kernel_launch(void* const* d_in, const int* in_sizes, int n_in,
                              void* d_out, int out_size) {
    const float4* X = (const float4*)d_in[0];
    float4* out = (float4*)d_out;
    lif_kernel<<<TOTAL4 / TPB, TPB>>>(X, out);
}

// round 13
// speedup vs baseline: 1.0136x; 1.0095x over previous
#include <cuda_runtime.h>

// LIF forward: X[B=128, T=32, N=8192] fp32 -> spikes fp32 (same shape).
// Per (b, n): mem = mem + (x_t - mem)/2 ; spike = mem > 1 ; mem = 0 on spike.
//
// R13 = locked R1 kernel + one single-variable probe: write-through stores
// (__stwt / st.global.wt). With default write-back, output lines sit dirty
// in L2 and drain in eviction bursts that collide with the inbound read
// stream at the DRAM scheduler; write-through streams them out continuously
// and leaves all L2 capacity to reads. Stores are already full-sector
// coalesced at issue, so no coalescing is lost.
//
// Context (11 prior rounds): touch-once 256 MiB stream; every well-formed
// variant (scalar, MLP, batched, TMA pipeline, reg-capped, .cs hints,
// phase-split, TPB=128) converges to kernel 38-41 us = ~7.0 TB/s effective
// (88% of 8 TB/s spec) — the mixed 50/50 R/W ceiling. Compute pipes idle.
// If this probe is neutral, R1 verbatim is the final committed kernel.

static constexpr int B = 128;
static constexpr int T = 32;
static constexpr int N = 8192;
static constexpr int N4 = N / 4;          // float4 columns per plane
static constexpr int TOTAL4 = B * N4;     // 262144 float4 lanes
static constexpr int TPB = 256;

__device__ __forceinline__ float4 step4(float4& m, const float4 x) {
    // exact reference rounding: mem += (x - mem) * 0.5f
    m.x = m.x + (x.x - m.x) * 0.5f;
    m.y = m.y + (x.y - m.y) * 0.5f;
    m.z = m.z + (x.z - m.z) * 0.5f;
    m.w = m.w + (x.w - m.w) * 0.5f;
    float4 s;
    s.x = (m.x > 1.0f) ? 1.0f : 0.0f;
    s.y = (m.y > 1.0f) ? 1.0f : 0.0f;
    s.z = (m.z > 1.0f) ? 1.0f : 0.0f;
    s.w = (m.w > 1.0f) ? 1.0f : 0.0f;
    // hard reset to 0 where spiked
    if (s.x != 0.0f) m.x = 0.0f;
    if (s.y != 0.0f) m.y = 0.0f;
    if (s.z != 0.0f) m.z = 0.0f;
    if (s.w != 0.0f) m.w = 0.0f;
    return s;
}

__global__ __launch_bounds__(TPB) void lif_kernel(const float4* __restrict__ X,
                                                  float4* __restrict__ out) {
    int idx = blockIdx.x * TPB + threadIdx.x;  // 0 .. TOTAL4-1
    if (idx >= TOTAL4) return;

    int b = idx / N4;
    int n4 = idx - b * N4;

    const float4* xp = X + (size_t)b * T * N4 + n4;
    float4* op = out + (size_t)b * T * N4 + n4;

    float4 m = make_float4(0.f, 0.f, 0.f, 0.f);

#pragma unroll
    for (int t = 0; t < T; t++) {
        float4 x = xp[(size_t)t * N4];
        float4 s = step4(m, x);
        __stwt(&op[(size_t)t * N4], s);   // write-through: no dirty-L2 burst drain
    }
}

extern "C" void kernel_launch(void* const* d_in, const int* in_sizes, int n_in,
                              void* d_out, int out_size) {
    const float4* X = (const float4*)d_in[0];
    float4* out = (float4*)d_out;
    lif_kernel<<<TOTAL4 / TPB, TPB>>>(X, out);
}